// round 2
// baseline (speedup 1.0000x reference)
#include <cuda_runtime.h>
#include <cstdint>

// ---------------------------------------------------------------------------
// LSTM_41764261986630 : 2-layer LSTM, T=512, B=64, IN=H=512
// Persistent weight-stationary kernel:
//   128 CTAs; CTA c: layer = c/64, owns 8 hidden units (= 32 ifgo rows, K=1024)
//   weights resident in SMEM; c-state in registers; one grid barrier per wave.
//   Wave w: layer0 computes step w, layer1 computes step w-1 (pipelined).
// ---------------------------------------------------------------------------

#define TSTEPS 512
#define BATCH  64
#define HID    512
#define G4     2048      // 4*H rows of ifgo per layer
#define NCTA   128
#define NTHR   128
#define ROWS   32        // ifgo rows per CTA = 4 gates x 8 hidden
#define HPC    8         // hidden units per CTA
#define WSTR   1028      // padded weight row stride (floats): bank shift 4 per row
#define KC     64        // k-chunk size
#define ASTR   68        // padded activation row stride (floats)
#define BH     (BATCH*HID)   // 32768

// persistent scratch (no cudaMalloc allowed)
__device__ float    g_h0[2][BH];   // double-buffered layer-0 hidden state
__device__ unsigned g_bar;         // monotonic grid-barrier counter (zero-init)

__device__ __forceinline__ void cp_async16(float* sdst, const float* gsrc) {
    unsigned sa = (unsigned)__cvta_generic_to_shared(sdst);
    asm volatile("cp.async.cg.shared.global [%0], [%1], 16;\n" :: "r"(sa), "l"(gsrc));
}
__device__ __forceinline__ void cp_commit() { asm volatile("cp.async.commit_group;\n"); }
__device__ __forceinline__ void cp_wait0()  { asm volatile("cp.async.wait_group 0;\n"); }

// Monotonic-counter grid barrier (works across graph replays: epoch-relative).
__device__ __forceinline__ void grid_sync() {
    __threadfence();
    __syncthreads();
    if (threadIdx.x == 0) {
        unsigned arrive = atomicAdd(&g_bar, 1u);
        unsigned target = (arrive / NCTA + 1u) * NCTA;
        while (*(volatile unsigned*)&g_bar < target) { __nanosleep(32); }
        __threadfence();
    }
    __syncthreads();
}

// Prefetch one 64x64 activation chunk (chunk c: c<8 -> srcA, else srcB)
__device__ __forceinline__ void prefetch_chunk(float* buf, const float* srcA,
                                               const float* srcB, int c, int tid) {
    const float* src = (c < 8) ? srcA : srcB;
    const int kb = (c & 7) * KC;
    #pragma unroll
    for (int it = 0; it < 8; ++it) {
        int flat = it * NTHR + tid;
        int b  = flat >> 4;      // batch row 0..63
        int kq = flat & 15;      // float4 index within chunk
        cp_async16(&buf[b * ASTR + kq * 4], src + b * HID + kb + kq * 4);
    }
    cp_commit();
}

__global__ void __launch_bounds__(NTHR, 1)
lstm_persistent(const float* __restrict__ x, const float* __restrict__ Wx,
                const float* __restrict__ Wh, const float* __restrict__ bh,
                float* __restrict__ out)
{
    extern __shared__ float smem[];
    float* w_s  = smem;                      // [32][1028]
    float* act0 = smem + ROWS * WSTR;        // [64][68]
    float* act1 = act0 + BATCH * ASTR;       // [64][68]

    const int tid   = threadIdx.x;
    const int cta   = blockIdx.x;
    const int layer = cta >> 6;              // 0 or 1
    const int hid0  = (cta & 63) * HPC;      // first hidden unit owned
    const int jj    = tid & 7;               // hidden within CTA (0..7)
    const int gidx  = tid >> 3;              // batch group (0..15); b = gidx + 16*i

    // ---- load this CTA's weight slice into SMEM (stationary for whole run) ----
    // row r = gate*8 + jr  <->  global ifgo row = gate*512 + hid0 + jr
    // k<512: input-weight (Wx for l0 acting on x_t; Wx for l1 acting on h0_t)
    // k>=512: recurrent weight Wh
    {
        const float* wx = Wx + (size_t)layer * G4 * HID;
        const float* wh = Wh + (size_t)layer * G4 * HID;
        for (int idx = tid; idx < ROWS * 256; idx += NTHR) {
            int r  = idx >> 8;
            int k  = (idx & 255) * 4;
            int gr = (r >> 3) * HID + hid0 + (r & 7);
            const float* s = (k < HID) ? (wx + (size_t)gr * HID + k)
                                       : (wh + (size_t)gr * HID + (k - HID));
            *(float4*)&w_s[r * WSTR + k] = *(const float4*)s;
        }
    }

    float bias[4];
    #pragma unroll
    for (int g = 0; g < 4; ++g)
        bias[g] = bh[layer * G4 + g * HID + hid0 + jj];

    const float* wrow[4];
    #pragma unroll
    for (int g = 0; g < 4; ++g) wrow[g] = &w_s[(g * 8 + jj) * WSTR];

    float c_st[4] = {0.f, 0.f, 0.f, 0.f};
    float h_st[4] = {0.f, 0.f, 0.f, 0.f};

    __syncthreads();   // weights ready (per-CTA)

    // ---- wave loop: 513 waves, 1 grid barrier each ----
    for (int w = 0; w <= TSTEPS; ++w) {
        const bool active = (layer == 0) ? (w < TSTEPS) : (w >= 1);
        if (active) {
            const int t = (layer == 0) ? w : (w - 1);
            const float* srcA;
            const float* srcB;
            if (layer == 0) {
                srcA = x + (size_t)t * BH;           // x_t
                srcB = g_h0[(t & 1) ^ 1];            // h0[t-1] (parity (t-1)&1)
            } else {
                srcA = g_h0[t & 1];                  // h0[t] (written last wave)
                srcB = out + (size_t)(t - 1) * BH;   // h1[t-1] lives in out
            }
            const int nchunk = (t == 0) ? 8 : 16;    // t==0: recurrent half is zero

            float acc[4][4];
            #pragma unroll
            for (int g = 0; g < 4; ++g)
                #pragma unroll
                for (int i = 0; i < 4; ++i) acc[g][i] = 0.f;

            prefetch_chunk(act0, srcA, srcB, 0, tid);

            for (int c = 0; c < nchunk; ++c) {
                cp_wait0();
                __syncthreads();
                if (c + 1 < nchunk)
                    prefetch_chunk((c & 1) ? act0 : act1, srcA, srcB, c + 1, tid);

                const float* ab  = (c & 1) ? act1 : act0;
                const float* ap0 = ab + (gidx     ) * ASTR;
                const float* ap1 = ab + (gidx + 16) * ASTR;
                const float* ap2 = ab + (gidx + 32) * ASTR;
                const float* ap3 = ab + (gidx + 48) * ASTR;
                const int kb = c * KC;

                #pragma unroll
                for (int k4 = 0; k4 < 16; ++k4) {
                    const int ko = k4 * 4;
                    float4 a0 = *(const float4*)(ap0 + ko);
                    float4 a1 = *(const float4*)(ap1 + ko);
                    float4 a2 = *(const float4*)(ap2 + ko);
                    float4 a3 = *(const float4*)(ap3 + ko);
                    #pragma unroll
                    for (int g = 0; g < 4; ++g) {
                        float4 wv = *(const float4*)(wrow[g] + kb + ko);
                        acc[g][0] += wv.x * a0.x; acc[g][0] += wv.y * a0.y;
                        acc[g][0] += wv.z * a0.z; acc[g][0] += wv.w * a0.w;
                        acc[g][1] += wv.x * a1.x; acc[g][1] += wv.y * a1.y;
                        acc[g][1] += wv.z * a1.z; acc[g][1] += wv.w * a1.w;
                        acc[g][2] += wv.x * a2.x; acc[g][2] += wv.y * a2.y;
                        acc[g][2] += wv.z * a2.z; acc[g][2] += wv.w * a2.w;
                        acc[g][3] += wv.x * a3.x; acc[g][3] += wv.y * a3.y;
                        acc[g][3] += wv.z * a3.z; acc[g][3] += wv.w * a3.w;
                    }
                }
            }

            // ---- gates + state update + publish h ----
            const int hh = hid0 + jj;
            float* hdst = (layer == 0) ? g_h0[t & 1] : (out + (size_t)t * BH);
            #pragma unroll
            for (int i = 0; i < 4; ++i) {
                float pi = acc[0][i] + bias[0];
                float pf = acc[1][i] + bias[1];
                float pg = acc[2][i] + bias[2];
                float po = acc[3][i] + bias[3];
                float ig = 1.f / (1.f + expf(-pi));
                float fg = 1.f / (1.f + expf(-pf));
                float gt = tanhf(pg);
                float og = 1.f / (1.f + expf(-po));
                float cn = fg * c_st[i] + ig * gt;
                c_st[i] = cn;
                float hn = og * tanhf(cn);
                h_st[i] = hn;
                int b = gidx + 16 * i;
                hdst[b * HID + hh] = hn;
            }
        }
        grid_sync();
    }

    // ---- final h, c tails: out layout = [out | h(L,B,H) | c(L,B,H)] ----
    const size_t base = (size_t)TSTEPS * BH;
    const int hh = hid0 + jj;
    #pragma unroll
    for (int i = 0; i < 4; ++i) {
        int b = gidx + 16 * i;
        out[base + (size_t)layer * BH + (size_t)b * HID + hh] = h_st[i];
        out[base + 2 * (size_t)BH + (size_t)layer * BH + (size_t)b * HID + hh] = c_st[i];
    }
}

extern "C" void kernel_launch(void* const* d_in, const int* in_sizes, int n_in,
                              void* d_out, int out_size) {
    (void)in_sizes; (void)n_in; (void)out_size;
    const float* x  = (const float*)d_in[0];
    const float* Wx = (const float*)d_in[1];
    const float* Wh = (const float*)d_in[2];
    const float* bh = (const float*)d_in[3];
    float* out = (float*)d_out;

    const int smem_bytes = (ROWS * WSTR + 2 * BATCH * ASTR) * (int)sizeof(float); // 166400
    cudaFuncSetAttribute(lstm_persistent,
                         cudaFuncAttributeMaxDynamicSharedMemorySize, smem_bytes);
    lstm_persistent<<<NCTA, NTHR, smem_bytes>>>(x, Wx, Wh, bh, out);
}